// round 4
// baseline (speedup 1.0000x reference)
#include <cuda_runtime.h>
#include <math.h>

// Shapes fixed: x, target = [B=8, C=256, H=128, W=128] fp32.
#define B_DIM    8
#define C_DIM    256
#define HW_DIM   (128 * 128)                // 16384 floats per (b,c) slab
#define N_PER_C  ((float)(B_DIM * HW_DIM))  // 131072 elements per channel
#define SPLIT    2                          // chunks per slab (finer tail granule)
#define CHUNKS   (B_DIM * C_DIM * SPLIT)    // 4096 chunks of 8192 floats
#define CHUNK_F  (HW_DIM / SPLIT)           // 8192 floats per chunk
#define THREADS  256
#define F4_ITER  (CHUNK_F / (THREADS * 4))  // 8 float4 loads per thread per tensor

// Per-chunk partial sums, moment-major. chunk = ((b*256+c)<<1)|h.
// Fully rewritten every launch -> no init needed.
__device__ float g_part[10][CHUNKS];
__device__ unsigned int g_done;  // zero at load; last CTA resets to zero each launch

__device__ __forceinline__ float warp_red(float v) {
#pragma unroll
    for (int o = 16; o; o >>= 1) v += __shfl_xor_sync(0xffffffffu, v, o);
    return v;
}

__global__ __launch_bounds__(THREADS) void style_loss_kernel(
    const float* __restrict__ x, const float* __restrict__ y,
    float* __restrict__ out) {
    const int chunk = blockIdx.x;
    const size_t base = (size_t)chunk * CHUNK_F;
    const float4* __restrict__ x4 = (const float4*)(x + base);
    const float4* __restrict__ y4 = (const float4*)(y + base);
    const int tid = threadIdx.x;

    float sx1 = 0.f, sx2 = 0.f, sx3 = 0.f, sx4 = 0.f, sx5 = 0.f;
    float sy1 = 0.f, sy2 = 0.f, sy3 = 0.f, sy4 = 0.f, sy5 = 0.f;

#pragma unroll 4
    for (int i = 0; i < F4_ITER; i++) {
        float4 vx = __ldcs(&x4[tid + i * THREADS]);  // streamed: touched once
        float4 vy = __ldcs(&y4[tid + i * THREADS]);
#pragma unroll
        for (int l = 0; l < 4; l++) {
            float v = (l == 0) ? vx.x : (l == 1) ? vx.y : (l == 2) ? vx.z : vx.w;
            float v2 = v * v;
            float v3 = v2 * v;
            sx1 += v;
            sx2 += v2;
            sx3 += v3;
            sx4 = fmaf(v2, v2, sx4);
            sx5 = fmaf(v3, v2, sx5);
            float w = (l == 0) ? vy.x : (l == 1) ? vy.y : (l == 2) ? vy.z : vy.w;
            float w2 = w * w;
            float w3 = w2 * w;
            sy1 += w;
            sy2 += w2;
            sy3 += w3;
            sy4 = fmaf(w2, w2, sy4);
            sy5 = fmaf(w3, w2, sy5);
        }
    }

    sx1 = warp_red(sx1); sx2 = warp_red(sx2); sx3 = warp_red(sx3);
    sx4 = warp_red(sx4); sx5 = warp_red(sx5);
    sy1 = warp_red(sy1); sy2 = warp_red(sy2); sy3 = warp_red(sy3);
    sy4 = warp_red(sy4); sy5 = warp_red(sy5);

    __shared__ float sh[THREADS / 32][10];
    const int lane = tid & 31, wid = tid >> 5;
    if (lane == 0) {
        sh[wid][0] = sx1; sh[wid][1] = sx2; sh[wid][2] = sx3;
        sh[wid][3] = sx4; sh[wid][4] = sx5;
        sh[wid][5] = sy1; sh[wid][6] = sy2; sh[wid][7] = sy3;
        sh[wid][8] = sy4; sh[wid][9] = sy5;
    }
    __syncthreads();
    if (tid < 10) {
        float a = 0.f;
#pragma unroll
        for (int w = 0; w < THREADS / 32; w++) a += sh[w][tid];
        g_part[tid][chunk] = a;
    }

    // ---- last-block finalize (threadfence reduction pattern) ----
    __shared__ bool s_last;
    __threadfence();  // make this CTA's g_part writes visible at L2
    if (tid == 0) {
        unsigned int n = atomicAdd(&g_done, 1u);
        s_last = (n == (unsigned int)(CHUNKS - 1));
    }
    __syncthreads();
    if (!s_last) return;

    // We are the last CTA: all g_part writes are globally visible (each CTA
    // fenced before its atomicAdd). Read via L2 (__ldcg) — L1 is not coherent.
    const int c = tid;  // one thread per channel
    float s[10];
#pragma unroll
    for (int j = 0; j < 10; j++) s[j] = 0.f;
#pragma unroll
    for (int b = 0; b < B_DIM; b++) {
#pragma unroll
        for (int h = 0; h < SPLIT; h++) {
            const int idx = ((b * C_DIM + c) << 1) | h;
#pragma unroll
            for (int j = 0; j < 10; j++) s[j] += __ldcg(&g_part[j][idx]);
        }
    }
    const float inv = 1.0f / N_PER_C;
    float mux = s[0] * inv, r2x = s[1] * inv, r3x = s[2] * inv, r4x = s[3] * inv, r5x = s[4] * inv;
    float muy = s[5] * inv, r2y = s[6] * inv, r3y = s[7] * inv, r4y = s[8] * inv, r5y = s[9] * inv;

    float mux2 = mux * mux, muy2 = muy * muy;
    // exact binomial recovery of centered moments from raw moments
    float m2x = r2x - mux2;
    float m3x = r3x - 3.f * mux * r2x + 2.f * mux2 * mux;
    float m4x = r4x - 4.f * mux * r3x + 6.f * mux2 * r2x - 3.f * mux2 * mux2;
    float m5x = r5x - 5.f * mux * r4x + 10.f * mux2 * r3x - 10.f * mux2 * mux * r2x
              + 4.f * mux2 * mux2 * mux;
    float m2y = r2y - muy2;
    float m3y = r3y - 3.f * muy * r2y + 2.f * muy2 * muy;
    float m4y = r4y - 4.f * muy * r3y + 6.f * muy2 * r2y - 3.f * muy2 * muy2;
    float m5y = r5y - 5.f * muy * r4y + 10.f * muy2 * r3y - 10.f * muy2 * muy * r2y
              + 4.f * muy2 * muy2 * muy;

    float d1 = mux - muy, d2 = m2x - m2y, d3 = m3x - m3y, d4 = m4x - m4y, d5 = m5x - m5y;
    float q[5] = { d1 * d1, d2 * d2, d3 * d3, d4 * d4, d5 * d5 };

#pragma unroll
    for (int k = 0; k < 5; k++) {
#pragma unroll
        for (int o = 16; o; o >>= 1) q[k] += __shfl_xor_sync(0xffffffffu, q[k], o);
    }
    __shared__ float shq[8][5];
    if (lane == 0) {
#pragma unroll
        for (int k = 0; k < 5; k++) shq[wid][k] = q[k];
    }
    __syncthreads();
    if (tid == 0) {
        float tot[5] = {0, 0, 0, 0, 0};
#pragma unroll
        for (int w = 0; w < 8; w++)
#pragma unroll
            for (int k = 0; k < 5; k++) tot[k] += shq[w][k];
        out[0] = sqrtf(tot[0]) + sqrtf(tot[1]) + sqrtf(tot[2]) + sqrtf(tot[3]) + sqrtf(tot[4]);
        g_done = 0u;  // reset for next (graph-replayed) launch
    }
}

extern "C" void kernel_launch(void* const* d_in, const int* in_sizes, int n_in,
                              void* d_out, int out_size) {
    const float* x = (const float*)d_in[0];
    const float* t = (const float*)d_in[1];
    style_loss_kernel<<<CHUNKS, THREADS>>>(x, t, (float*)d_out);
}

// round 5
// speedup vs baseline: 1.0608x; 1.0608x over previous
#include <cuda_runtime.h>
#include <math.h>

// Shapes fixed: x, target = [B=8, C=256, H=128, W=128] fp32.
#define B_DIM    8
#define C_DIM    256
#define HW_DIM   (128 * 128)                // 16384 floats per (b,c) slab
#define N_PER_C  ((float)(B_DIM * HW_DIM))  // 131072 elements per channel
#define CHUNKS   (B_DIM * C_DIM)            // 2048 slabs, slab s = b*256 + c
#define THREADS  256
#define F4_ITER  (HW_DIM / (THREADS * 4))   // 16 float4 loads per thread per tensor

// Per-slab partial sums, moment-major. Fully rewritten every launch.
__device__ float g_part[10][CHUNKS];
__device__ unsigned int g_done;  // zero at load; last CTA resets it each launch

__device__ __forceinline__ float warp_red(float v) {
#pragma unroll
    for (int o = 16; o; o >>= 1) v += __shfl_xor_sync(0xffffffffu, v, o);
    return v;
}

__global__ __launch_bounds__(THREADS) void style_loss_kernel(
    const float* __restrict__ x, const float* __restrict__ y,
    float* __restrict__ out) {
    const int s = blockIdx.x;                       // flat slab: contiguous 64KB region
    const size_t base = (size_t)s * HW_DIM;
    const float4* __restrict__ x4 = (const float4*)(x + base);
    const float4* __restrict__ y4 = (const float4*)(y + base);
    const int tid = threadIdx.x;

    float sx1 = 0.f, sx2 = 0.f, sx3 = 0.f, sx4 = 0.f, sx5 = 0.f;
    float sy1 = 0.f, sy2 = 0.f, sy3 = 0.f, sy4 = 0.f, sy5 = 0.f;

#pragma unroll 4
    for (int i = 0; i < F4_ITER; i++) {
        float4 vx = __ldcs(&x4[tid + i * THREADS]);  // streamed: touched once
        float4 vy = __ldcs(&y4[tid + i * THREADS]);
#pragma unroll
        for (int l = 0; l < 4; l++) {
            float v = (l == 0) ? vx.x : (l == 1) ? vx.y : (l == 2) ? vx.z : vx.w;
            float v2 = v * v;
            float v3 = v2 * v;
            sx1 += v;
            sx2 += v2;
            sx3 += v3;
            sx4 = fmaf(v2, v2, sx4);
            sx5 = fmaf(v3, v2, sx5);
            float w = (l == 0) ? vy.x : (l == 1) ? vy.y : (l == 2) ? vy.z : vy.w;
            float w2 = w * w;
            float w3 = w2 * w;
            sy1 += w;
            sy2 += w2;
            sy3 += w3;
            sy4 = fmaf(w2, w2, sy4);
            sy5 = fmaf(w3, w2, sy5);
        }
    }

    sx1 = warp_red(sx1); sx2 = warp_red(sx2); sx3 = warp_red(sx3);
    sx4 = warp_red(sx4); sx5 = warp_red(sx5);
    sy1 = warp_red(sy1); sy2 = warp_red(sy2); sy3 = warp_red(sy3);
    sy4 = warp_red(sy4); sy5 = warp_red(sy5);

    __shared__ float sh[THREADS / 32][10];
    const int lane = tid & 31, wid = tid >> 5;
    if (lane == 0) {
        sh[wid][0] = sx1; sh[wid][1] = sx2; sh[wid][2] = sx3;
        sh[wid][3] = sx4; sh[wid][4] = sx5;
        sh[wid][5] = sy1; sh[wid][6] = sy2; sh[wid][7] = sy3;
        sh[wid][8] = sy4; sh[wid][9] = sy5;
    }
    __syncthreads();
    if (tid < 10) {
        float a = 0.f;
#pragma unroll
        for (int w = 0; w < THREADS / 32; w++) a += sh[w][tid];
        g_part[tid][s] = a;
    }

    // ---- last-block finalize (threadfence reduction pattern) ----
    __shared__ bool s_last;
    __threadfence();  // make this CTA's g_part writes visible at L2
    if (tid == 0) {
        unsigned int n = atomicAdd(&g_done, 1u);
        s_last = (n == (unsigned int)(CHUNKS - 1));
    }
    __syncthreads();
    if (!s_last) return;

    // Last CTA: all g_part writes globally visible (each CTA fenced before its
    // atomicAdd). Read via L2 (__ldcg) — L1 is not coherent across SMs.
    const int c = tid;  // one thread per channel
    float sm[10];
#pragma unroll
    for (int j = 0; j < 10; j++) sm[j] = 0.f;
#pragma unroll
    for (int b = 0; b < B_DIM; b++) {
#pragma unroll
        for (int j = 0; j < 10; j++)
            sm[j] += __ldcg(&g_part[j][b * C_DIM + c]);  // coalesced, lane stride 4B
    }
    const float inv = 1.0f / N_PER_C;
    float mux = sm[0] * inv, r2x = sm[1] * inv, r3x = sm[2] * inv, r4x = sm[3] * inv, r5x = sm[4] * inv;
    float muy = sm[5] * inv, r2y = sm[6] * inv, r3y = sm[7] * inv, r4y = sm[8] * inv, r5y = sm[9] * inv;

    float mux2 = mux * mux, muy2 = muy * muy;
    // exact binomial recovery of centered moments from raw moments
    float m2x = r2x - mux2;
    float m3x = r3x - 3.f * mux * r2x + 2.f * mux2 * mux;
    float m4x = r4x - 4.f * mux * r3x + 6.f * mux2 * r2x - 3.f * mux2 * mux2;
    float m5x = r5x - 5.f * mux * r4x + 10.f * mux2 * r3x - 10.f * mux2 * mux * r2x
              + 4.f * mux2 * mux2 * mux;
    float m2y = r2y - muy2;
    float m3y = r3y - 3.f * muy * r2y + 2.f * muy2 * muy;
    float m4y = r4y - 4.f * muy * r3y + 6.f * muy2 * r2y - 3.f * muy2 * muy2;
    float m5y = r5y - 5.f * muy * r4y + 10.f * muy2 * r3y - 10.f * muy2 * muy * r2y
              + 4.f * muy2 * muy2 * muy;

    float d1 = mux - muy, d2 = m2x - m2y, d3 = m3x - m3y, d4 = m4x - m4y, d5 = m5x - m5y;
    float q[5] = { d1 * d1, d2 * d2, d3 * d3, d4 * d4, d5 * d5 };

#pragma unroll
    for (int k = 0; k < 5; k++) {
#pragma unroll
        for (int o = 16; o; o >>= 1) q[k] += __shfl_xor_sync(0xffffffffu, q[k], o);
    }
    __shared__ float shq[8][5];
    if (lane == 0) {
#pragma unroll
        for (int k = 0; k < 5; k++) shq[wid][k] = q[k];
    }
    __syncthreads();
    if (tid == 0) {
        float tot[5] = {0, 0, 0, 0, 0};
#pragma unroll
        for (int w = 0; w < 8; w++)
#pragma unroll
            for (int k = 0; k < 5; k++) tot[k] += shq[w][k];
        out[0] = sqrtf(tot[0]) + sqrtf(tot[1]) + sqrtf(tot[2]) + sqrtf(tot[3]) + sqrtf(tot[4]);
        g_done = 0u;  // reset for next (graph-replayed) launch
    }
}

extern "C" void kernel_launch(void* const* d_in, const int* in_sizes, int n_in,
                              void* d_out, int out_size) {
    const float* x = (const float*)d_in[0];
    const float* t = (const float*)d_in[1];
    style_loss_kernel<<<CHUNKS, THREADS>>>(x, t, (float*)d_out);
}

// round 6
// speedup vs baseline: 1.1905x; 1.1223x over previous
#include <cuda_runtime.h>
#include <math.h>

// Shapes fixed: x, target = [B=8, C=256, H=128, W=128] fp32.
#define B_DIM   8
#define C_DIM   256
#define HW_DIM  (128 * 128)                 // 16384 floats per (b,c) slab
#define N_PER_C ((float)(B_DIM * HW_DIM))   // 131072 elements per channel
#define SLABS   (B_DIM * C_DIM)             // 2048 flat slabs, slab s = b*256 + c
#define THREADS 256
#define P2_ITER (HW_DIM / (THREADS * 4))    // 16 ulonglong2 loads (4 floats) per thread/tensor

// Per-slab partial sums, moment-major for coalesced finalize reads.
__device__ float g_part[10][SLABS];

typedef unsigned long long ull;

// Blackwell packed f32x2 ops (FMA pipe, 2 floats per instruction; PTX-only).
__device__ __forceinline__ ull mul2(ull a, ull b) {
    ull r; asm("mul.rn.f32x2 %0, %1, %2;" : "=l"(r) : "l"(a), "l"(b)); return r;
}
__device__ __forceinline__ ull add2(ull a, ull b) {
    ull r; asm("add.rn.f32x2 %0, %1, %2;" : "=l"(r) : "l"(a), "l"(b)); return r;
}
__device__ __forceinline__ ull fma2(ull a, ull b, ull c) {
    ull r; asm("fma.rn.f32x2 %0, %1, %2, %3;" : "=l"(r) : "l"(a), "l"(b), "l"(c)); return r;
}
__device__ __forceinline__ float unpack_sum(ull p) {
    unsigned int lo = (unsigned int)p, hi = (unsigned int)(p >> 32);
    return __uint_as_float(lo) + __uint_as_float(hi);
}

__device__ __forceinline__ float warp_red(float v) {
#pragma unroll
    for (int o = 16; o; o >>= 1) v += __shfl_xor_sync(0xffffffffu, v, o);
    return v;
}

__global__ __launch_bounds__(THREADS) void moments_kernel(
    const float* __restrict__ x, const float* __restrict__ y) {
    const int s = blockIdx.x;                       // contiguous 64KB slab
    const size_t base = (size_t)s * HW_DIM;
    const ulonglong2* __restrict__ x2 = (const ulonglong2*)(x + base);
    const ulonglong2* __restrict__ y2 = (const ulonglong2*)(y + base);
    const int tid = threadIdx.x;

    // f32x2 accumulators: each holds 2 reduction lanes.
    ull sx1 = 0, sx2 = 0, sx3 = 0, sx4 = 0, sx5 = 0;
    ull sy1 = 0, sy2 = 0, sy3 = 0, sy4 = 0, sy5 = 0;

#pragma unroll 4
    for (int i = 0; i < P2_ITER; i++) {
        ulonglong2 vx = __ldcs(&x2[tid + i * THREADS]);  // 4 floats, streamed
        ulonglong2 vy = __ldcs(&y2[tid + i * THREADS]);
#pragma unroll
        for (int l = 0; l < 2; l++) {
            ull p = (l == 0) ? vx.x : vx.y;
            ull p2 = mul2(p, p);
            ull p3 = mul2(p2, p);
            sx1 = add2(sx1, p);
            sx2 = add2(sx2, p2);
            sx3 = add2(sx3, p3);
            sx4 = fma2(p2, p2, sx4);
            sx5 = fma2(p3, p2, sx5);
            ull q = (l == 0) ? vy.x : vy.y;
            ull q2 = mul2(q, q);
            ull q3 = mul2(q2, q);
            sy1 = add2(sy1, q);
            sy2 = add2(sy2, q2);
            sy3 = add2(sy3, q3);
            sy4 = fma2(q2, q2, sy4);
            sy5 = fma2(q3, q2, sy5);
        }
    }

    // Collapse packed lanes, then fp32 warp tree-reduce.
    float a1 = warp_red(unpack_sum(sx1)), a2 = warp_red(unpack_sum(sx2));
    float a3 = warp_red(unpack_sum(sx3)), a4 = warp_red(unpack_sum(sx4));
    float a5 = warp_red(unpack_sum(sx5));
    float b1 = warp_red(unpack_sum(sy1)), b2 = warp_red(unpack_sum(sy2));
    float b3 = warp_red(unpack_sum(sy3)), b4 = warp_red(unpack_sum(sy4));
    float b5 = warp_red(unpack_sum(sy5));

    __shared__ float sh[THREADS / 32][10];
    const int lane = tid & 31, wid = tid >> 5;
    if (lane == 0) {
        sh[wid][0] = a1; sh[wid][1] = a2; sh[wid][2] = a3; sh[wid][3] = a4; sh[wid][4] = a5;
        sh[wid][5] = b1; sh[wid][6] = b2; sh[wid][7] = b3; sh[wid][8] = b4; sh[wid][9] = b5;
    }
    __syncthreads();
    if (tid < 10) {
        float a = 0.f;
#pragma unroll
        for (int w = 0; w < THREADS / 32; w++) a += sh[w][tid];
        g_part[tid][s] = a;
    }
}

// All-fp32 finalize (fp64 pipe on B300 is ~35x slower than FFMA — avoid).
__global__ __launch_bounds__(C_DIM) void finalize_kernel(float* __restrict__ out) {
    const int c = threadIdx.x;  // one thread per channel; lanes consecutive in c

    float s[10];
#pragma unroll
    for (int j = 0; j < 10; j++) s[j] = 0.f;
#pragma unroll
    for (int b = 0; b < B_DIM; b++) {
#pragma unroll
        for (int j = 0; j < 10; j++)
            s[j] += g_part[j][b * C_DIM + c];  // coalesced, L2-hot
    }
    const float inv = 1.0f / N_PER_C;
    float mux = s[0] * inv, r2x = s[1] * inv, r3x = s[2] * inv, r4x = s[3] * inv, r5x = s[4] * inv;
    float muy = s[5] * inv, r2y = s[6] * inv, r3y = s[7] * inv, r4y = s[8] * inv, r5y = s[9] * inv;

    float mux2 = mux * mux, muy2 = muy * muy;
    // exact binomial recovery of centered moments from raw moments
    float m2x = r2x - mux2;
    float m3x = r3x - 3.f * mux * r2x + 2.f * mux2 * mux;
    float m4x = r4x - 4.f * mux * r3x + 6.f * mux2 * r2x - 3.f * mux2 * mux2;
    float m5x = r5x - 5.f * mux * r4x + 10.f * mux2 * r3x - 10.f * mux2 * mux * r2x
              + 4.f * mux2 * mux2 * mux;
    float m2y = r2y - muy2;
    float m3y = r3y - 3.f * muy * r2y + 2.f * muy2 * muy;
    float m4y = r4y - 4.f * muy * r3y + 6.f * muy2 * r2y - 3.f * muy2 * muy2;
    float m5y = r5y - 5.f * muy * r4y + 10.f * muy2 * r3y - 10.f * muy2 * muy * r2y
              + 4.f * muy2 * muy2 * muy;

    float d1 = mux - muy, d2 = m2x - m2y, d3 = m3x - m3y, d4 = m4x - m4y, d5 = m5x - m5y;
    float q[5] = { d1 * d1, d2 * d2, d3 * d3, d4 * d4, d5 * d5 };

#pragma unroll
    for (int k = 0; k < 5; k++) {
#pragma unroll
        for (int o = 16; o; o >>= 1) q[k] += __shfl_xor_sync(0xffffffffu, q[k], o);
    }
    __shared__ float shq[8][5];
    const int lane = c & 31, wid = c >> 5;
    if (lane == 0) {
#pragma unroll
        for (int k = 0; k < 5; k++) shq[wid][k] = q[k];
    }
    __syncthreads();
    if (c == 0) {
        float tot[5] = {0, 0, 0, 0, 0};
#pragma unroll
        for (int w = 0; w < 8; w++)
#pragma unroll
            for (int k = 0; k < 5; k++) tot[k] += shq[w][k];
        out[0] = sqrtf(tot[0]) + sqrtf(tot[1]) + sqrtf(tot[2]) + sqrtf(tot[3]) + sqrtf(tot[4]);
    }
}

extern "C" void kernel_launch(void* const* d_in, const int* in_sizes, int n_in,
                              void* d_out, int out_size) {
    const float* x = (const float*)d_in[0];
    const float* t = (const float*)d_in[1];
    moments_kernel<<<SLABS, THREADS>>>(x, t);
    finalize_kernel<<<1, C_DIM>>>((float*)d_out);
}